// round 17
// baseline (speedup 1.0000x reference)
#include <cuda_runtime.h>
#include <cuda_fp16.h>

// NeuralVoxelField: trilinear interp of 2M random points into a 128^3 x16 grid.
//
// R16 = R15 + two-deep software pipeline in the interp loop:
//  gathers for chunk i+1 are issued BEFORE the math of chunk i runs, so each
//  chunk's 4 gathers get a full loop iteration of latency hiding (R15 only
//  prefetched coords; math stalled ~30 instrs after its own gathers issued).
//  Loop unrolled 2x (A/B register buffers, no rotation MOVs); prefetch chunk
//  indices clamped so all loads are safe; stores predicated on p<n.
// Convert pass unchanged (8 floats/thread, evict_last-hinted fp16 stores).

constexpr int Dg = 128, Hg = 128, Wg = 128, Cg = 16;
constexpr float INV_VOXEL = 20.0f;               // 1/0.05
constexpr int NVOX   = Dg * Hg * Wg;
constexpr int NHALF  = NVOX * Cg;                // 64MB of halves
constexpr int NELEM8 = NHALF / 8;

__device__ __align__(16) __half d_grid_h[NHALF];

__device__ __forceinline__ unsigned long long mk_evict_last_policy() {
    unsigned long long pol;
    asm("createpolicy.fractional.L2::evict_last.b64 %0, 1.0;" : "=l"(pol));
    return pol;
}

// ---- pass 1: fp32 grid -> fp16 scratch, stores biased evict_last ----
__global__ __launch_bounds__(256)
void convert_kernel(const float4* __restrict__ values) {
    int i = blockIdx.x * blockDim.x + threadIdx.x;
    if (i >= NELEM8) return;
    float4 v0 = __ldcs(&values[i * 2 + 0]);      // evict-first: read once
    float4 v1 = __ldcs(&values[i * 2 + 1]);
    uint4 u;
    __half2 h;
    h = __float22half2_rn(make_float2(v0.x, v0.y)); u.x = *(unsigned*)&h;
    h = __float22half2_rn(make_float2(v0.z, v0.w)); u.y = *(unsigned*)&h;
    h = __float22half2_rn(make_float2(v1.x, v1.y)); u.z = *(unsigned*)&h;
    h = __float22half2_rn(make_float2(v1.z, v1.w)); u.w = *(unsigned*)&h;
    unsigned long long pol = mk_evict_last_policy();
    asm volatile("st.global.L2::cache_hint.v4.u32 [%0], {%1,%2,%3,%4}, %5;"
                 :: "l"(d_grid_h + (size_t)i * 8),
                    "r"(u.x), "r"(u.y), "r"(u.z), "r"(u.w), "l"(pol)
                 : "memory");
}

// per-chunk context saved between issue and math (3 regs)
struct ChunkW {
    __half2 xd2, yd2;
    float   wa;
};

// shfl coords, compute addresses, ISSUE the 4 gathers; save weights.
__device__ __forceinline__ ChunkW issue_chunk(float fload, int q, int l, bool v,
                                              uint4* buf) {
    float x = __shfl_sync(0xffffffffu, fload, q * 3 + 0) * INV_VOXEL;
    float y = __shfl_sync(0xffffffffu, fload, q * 3 + 1) * INV_VOXEL;
    float z = __shfl_sync(0xffffffffu, fload, q * 3 + 2) * INV_VOXEL;

    int x0 = __float2int_rd(x);
    int y0 = __float2int_rd(y);
    int z0 = __float2int_rd(z);
    int x1 = min(x0 + 1, Dg - 1);
    int y1 = min(y0 + 1, Hg - 1);
    int zp = min(z0, Wg - 2);

    ChunkW w;
    w.xd2 = __float2half2_rn(x - (float)x0);
    w.yd2 = __float2half2_rn(y - (float)y0);
    float zd = z - (float)z0;
    float w1 = (z0 == Wg - 1) ? 1.0f : zd;
    w.wa = v ? w1 : (1.0f - w1);

    int zb  = zp * Cg + l * 8;
    int a00 = ((x0 * Hg + y0) * Wg) * Cg + zb;
    int a01 = ((x0 * Hg + y1) * Wg) * Cg + zb;
    int a10 = ((x1 * Hg + y0) * Wg) * Cg + zb;
    int a11 = ((x1 * Hg + y1) * Wg) * Cg + zb;

    const __half* g = d_grid_h;
    buf[0] = __ldg((const uint4*)(g + a00));
    buf[1] = __ldg((const uint4*)(g + a01));
    buf[2] = __ldg((const uint4*)(g + a10));
    buf[3] = __ldg((const uint4*)(g + a11));
    return w;
}

// consume gathered corners, lerp, z-combine, store.
__device__ __forceinline__ void math_store(const uint4* buf, const ChunkW& w,
                                           int pbase, int q, int l, bool v,
                                           int n, float4* __restrict__ out) {
    const __half2* b00 = reinterpret_cast<const __half2*>(&buf[0]);
    const __half2* b01 = reinterpret_cast<const __half2*>(&buf[1]);
    const __half2* b10 = reinterpret_cast<const __half2*>(&buf[2]);
    const __half2* b11 = reinterpret_cast<const __half2*>(&buf[3]);

    float m[8];
    #pragma unroll
    for (int i = 0; i < 4; i++) {
        __half2 t0 = __hfma2(__hsub2(b01[i], b00[i]), w.yd2, b00[i]); // @x0
        __half2 t1 = __hfma2(__hsub2(b11[i], b10[i]), w.yd2, b10[i]); // @x1
        __half2 r  = __hfma2(__hsub2(t1, t0), w.xd2, t0);
        float2 f = __half22float2(r);
        m[i * 2 + 0] = f.x * w.wa;
        m[i * 2 + 1] = f.y * w.wa;
    }

    float keep[4], send[4];
    #pragma unroll
    for (int j = 0; j < 4; j++) {
        keep[j] = v ? m[4 + j] : m[j];
        send[j] = v ? m[j] : m[4 + j];
    }
    float res[4];
    #pragma unroll
    for (int j = 0; j < 4; j++)
        res[j] = keep[j] + __shfl_xor_sync(0xffffffffu, send[j], 2);

    int p = pbase + q;
    int slot = ((l & 1) << 1) | (int)v;
    if (p < n)
        __stcs(&out[p * 4 + slot], make_float4(res[0], res[1], res[2], res[3]));
}

__global__ __launch_bounds__(256, 4)
void interp_kernel(const float* __restrict__ points,
                   float4* __restrict__ out,     // (N,16) fp32 as float4
                   int n, int nchunks)
{
    int la = threadIdx.x & 31;           // lane in warp
    int q  = la >> 2;                    // point-in-warp 0..7
    int l  = la & 3;                     // lane-in-point
    bool v = (l >> 1) != 0;              // my z-level

    int warpId = (blockIdx.x * blockDim.x + threadIdx.x) >> 5;
    int s      = (gridDim.x * blockDim.x) >> 5;   // warp stride
    int n3 = n * 3;

    if (warpId >= nchunks) return;

    // clamped coalesced coord load (always safe; tail predicated at store)
    auto ldc = [&](int cc) -> float {
        int cm = min(cc, nchunks - 1);
        int ci = cm * 24 + la;
        return (la < 24 && ci < n3) ? __ldcs(&points[ci]) : 0.0f;
    };

    int cA = warpId;
    float coA = ldc(cA);                  // coords(cA)
    uint4 A[4];
    ChunkW wA = issue_chunk(coA, q, l, v, A);   // gathers(cA) in flight
    float coB = ldc(cA + s);              // coords(cA+s)

    for (;;) {
        // half 1: launch B(cA+s), prefetch coords(cA+2s), process A(cA)
        uint4 B[4];
        ChunkW wB = issue_chunk(coB, q, l, v, B);
        float coN = ldc(cA + 2 * s);
        math_store(A, wA, cA * 8, q, l, v, n, out);
        int cB = cA + s;
        if (cB >= nchunks) return;

        // half 2: launch A(cB+s) from coN, prefetch coords(cB+2s), process B
        wA = issue_chunk(coN, q, l, v, A);
        float coM = ldc(cB + 2 * s);
        math_store(B, wB, cB * 8, q, l, v, n, out);
        cA = cB + s;
        if (cA >= nchunks) return;

        coB = coM;                        // coords(cA+s)
    }
}

extern "C" void kernel_launch(void* const* d_in, const int* in_sizes, int n_in,
                              void* d_out, int out_size) {
    const float*  points = (const float*)d_in[0];    // (N,3) fp32
    const float4* values = (const float4*)d_in[1];   // (128,128,128,16) fp32
    float4* out = (float4*)d_out;

    int n = in_sizes[0] / 3;
    int T = 256;

    convert_kernel<<<(NELEM8 + T - 1) / T, T>>>(values);

    int nchunks = (n + 7) / 8;           // 8 points per warp-chunk
    int blocks = 4096;
    interp_kernel<<<blocks, T>>>(points, out, n, nchunks);
}